// round 3
// baseline (speedup 1.0000x reference)
#include <cuda_runtime.h>
#include <cuda_bf16.h>

// VertexDistExtract3D: for each of B rows, x = [pos(3), quat(4), verts(64x3)];
// out[b,k,p] = dot(R(q) @ v_k + pos, dir_p), P=4 dirs.
// Rearranged: M = dirs @ R (4x3), off = dirs @ pos (4); out[k] = M @ v_k + off.
// HBM-bound: ~238 MB traffic/launch. Staging: 16 rows * 199 floats = 3184
// floats = 796 float4 per block, base 16B-aligned (row0 % 16 == 0).

#define KVERTS 64
#define DROW   199     // 7 + 3*64
#define ROWS_PER_BLOCK 16
#define NTHREADS 512
#define BLOCK_FLOATS (ROWS_PER_BLOCK * DROW)   // 3184
#define BLOCK_VEC4   (BLOCK_FLOATS / 4)        // 796

__global__ __launch_bounds__(NTHREADS)
void vde_kernel(const float* __restrict__ x,
                const float* __restrict__ dirs,
                float* __restrict__ out,
                int B)
{
    __shared__ float s[BLOCK_FLOATS];
    __shared__ float sd[12];

    const int tid = threadIdx.x;
    const long long row0 = (long long)blockIdx.x * ROWS_PER_BLOCK;

    if (tid < 12) sd[tid] = dirs[tid];

    long long rows_here = B - row0;
    if (rows_here > ROWS_PER_BLOCK) rows_here = ROWS_PER_BLOCK;

    if (rows_here == ROWS_PER_BLOCK) {
        // Full block: vectorized staging with two independent LDG.128 per
        // thread (796 = 512 + 284) so both loads are in flight together.
        const float4* __restrict__ g4 =
            reinterpret_cast<const float4*>(x + row0 * DROW);
        float4* s4 = reinterpret_cast<float4*>(s);

        const int i0 = tid;
        const int i1 = tid + NTHREADS;
        float4 a = g4[i0];                       // always in range (i0 < 512 <= 796)
        float4 b;
        const bool has_b = (i1 < BLOCK_VEC4);
        if (has_b) b = g4[i1];
        s4[i0] = a;
        if (has_b) s4[i1] = b;
    } else {
        // Tail (unused for B=131072, kept for safety): scalar staging.
        const int total = (int)rows_here * DROW;
        const float* g = x + row0 * DROW;
        for (int i = tid; i < total; i += NTHREADS)
            s[i] = g[i];
    }
    __syncthreads();

    const int lane = tid & 31;
    const int r    = tid >> 5;
    const long long row = row0 + r;
    if (row >= B) return;

    const float* rs = s + r * DROW;

    const float px = rs[0], py = rs[1], pz = rs[2];
    const float qw = rs[3], qx = rs[4], qy = rs[5], qz = rs[6];

    // Unit-quaternion rotation matrix (matches reference formula, no normalize).
    const float R00 = 1.f - 2.f * (qy * qy + qz * qz);
    const float R01 = 2.f * (qx * qy - qz * qw);
    const float R02 = 2.f * (qx * qz + qy * qw);
    const float R10 = 2.f * (qx * qy + qz * qw);
    const float R11 = 1.f - 2.f * (qx * qx + qz * qz);
    const float R12 = 2.f * (qy * qz - qx * qw);
    const float R20 = 2.f * (qx * qz - qy * qw);
    const float R21 = 2.f * (qy * qz + qx * qw);
    const float R22 = 1.f - 2.f * (qx * qx + qy * qy);

    float M[4][3], off[4];
#pragma unroll
    for (int p = 0; p < 4; p++) {
        const float e0 = sd[p * 3 + 0];
        const float e1 = sd[p * 3 + 1];
        const float e2 = sd[p * 3 + 2];
        M[p][0] = fmaf(e0, R00, fmaf(e1, R10, e2 * R20));
        M[p][1] = fmaf(e0, R01, fmaf(e1, R11, e2 * R21));
        M[p][2] = fmaf(e0, R02, fmaf(e1, R12, e2 * R22));
        off[p]  = fmaf(e0, px,  fmaf(e1, py,  e2 * pz));
    }

    // Output row = 64 float4; d_out 256B-aligned, row stride 1024B.
    float4* outv = reinterpret_cast<float4*>(out) + row * KVERTS;

#pragma unroll
    for (int t = 0; t < 2; t++) {
        const int k = lane + 32 * t;
        const float v0 = rs[7 + 3 * k];
        const float v1 = rs[8 + 3 * k];
        const float v2 = rs[9 + 3 * k];
        float4 o;
        o.x = fmaf(M[0][0], v0, fmaf(M[0][1], v1, fmaf(M[0][2], v2, off[0])));
        o.y = fmaf(M[1][0], v0, fmaf(M[1][1], v1, fmaf(M[1][2], v2, off[1])));
        o.z = fmaf(M[2][0], v0, fmaf(M[2][1], v1, fmaf(M[2][2], v2, off[2])));
        o.w = fmaf(M[3][0], v0, fmaf(M[3][1], v1, fmaf(M[3][2], v2, off[3])));
        outv[k] = o;
    }
}

extern "C" void kernel_launch(void* const* d_in, const int* in_sizes, int n_in,
                              void* d_out, int out_size)
{
    const float* x    = (const float*)d_in[0];
    const float* dirs = (const float*)d_in[1];
    float* out        = (float*)d_out;

    const int B = in_sizes[0] / DROW;   // x is (B,1,199) fp32
    const int grid = (B + ROWS_PER_BLOCK - 1) / ROWS_PER_BLOCK;
    vde_kernel<<<grid, NTHREADS>>>(x, dirs, out, B);
}

// round 6
// speedup vs baseline: 1.1140x; 1.1140x over previous
#include <cuda_runtime.h>
#include <cuda_bf16.h>
#include <cstdint>

// VertexDistExtract3D: x row = [pos(3), quat(4), verts(64x3)];
// out[b,k,p] = dot(R(q) @ v_k + pos, dir_p), P=4.
// Folded: M = dirs @ R (4x3), off = dirs @ pos; out[k] = M @ v_k + off.
//
// Measured baseline (LDG version): 47.8us, DRAM 55%, issue 50%, fma 27%,
// L1 45% -> latency-bound bursty phases + 32x redundant M compute per row.
// This version: cp.async.bulk staging, 2-deep ring, 8 tiles/block (single
// wave at 8 CTAs/SM), 16 threads/row (4 verts/lane, half the redundant FMA).

#define DROW        199                  // 7 + 3*64
#define KVERTS      64
#define TILE_ROWS   16
#define TILE_FLOATS (TILE_ROWS * DROW)   // 3184
#define TILE_BYTES  (TILE_FLOATS * 4)    // 12736, multiple of 16
#define NTHREADS    256
#define TPB_TILES   8                    // tiles per block

__device__ __forceinline__ uint32_t smem_u32(const void* p) {
    uint32_t a;
    asm("{ .reg .u64 t; cvta.to.shared.u64 t, %1; cvt.u32.u64 %0, t; }"
        : "=r"(a) : "l"(p));
    return a;
}

#define MBAR_INIT(mb, cnt) \
    asm volatile("mbarrier.init.shared.b64 [%0], %1;" :: "r"(mb), "r"(cnt) : "memory")

#define MBAR_EXPECT_TX(mb, bytes) \
    asm volatile("mbarrier.arrive.expect_tx.shared.b64 _, [%0], %1;" \
                 :: "r"(mb), "r"(bytes) : "memory")

#define BULK_G2S(dst, src, bytes, mb) \
    asm volatile("cp.async.bulk.shared::cta.global.mbarrier::complete_tx::bytes " \
                 "[%0], [%1], %2, [%3];" \
                 :: "r"(dst), "l"(src), "r"(bytes), "r"(mb) : "memory")

#define MBAR_WAIT(mb, parity) do {                                              \
    asm volatile(                                                               \
        "{\n\t.reg .pred P1;\n\t"                                               \
        "WAIT_LOOP_%=:\n\t"                                                     \
        "mbarrier.try_wait.parity.acquire.cta.shared::cta.b64 P1, [%0], %1, 0x989680;\n\t" \
        "@P1 bra.uni WAIT_DONE_%=;\n\t"                                         \
        "bra.uni WAIT_LOOP_%=;\n\t"                                             \
        "WAIT_DONE_%=:\n\t}"                                                    \
        :: "r"(mb), "r"(parity) : "memory");                                    \
} while (0)

__global__ __launch_bounds__(NTHREADS)
void vde_kernel(const float* __restrict__ x,
                const float* __restrict__ dirs,
                float* __restrict__ out,
                int n_tiles)
{
    __shared__ __align__(16) float buf[2][TILE_FLOATS];
    __shared__ __align__(8)  uint64_t mbar[2];
    __shared__ float sd[12];

    const int tid = threadIdx.x;
    if (tid < 12) sd[tid] = dirs[tid];
    if (tid == 0) {
        MBAR_INIT(smem_u32(&mbar[0]), 1);
        MBAR_INIT(smem_u32(&mbar[1]), 1);
    }
    __syncthreads();

    const int tile0 = blockIdx.x * TPB_TILES;
    int my_tiles = n_tiles - tile0;
    if (my_tiles > TPB_TILES) my_tiles = TPB_TILES;
    if (my_tiles <= 0) return;

    // Prologue: kick off tile 0 load.
    if (tid == 0) {
        const uint32_t mb = smem_u32(&mbar[0]);
        MBAR_EXPECT_TX(mb, TILE_BYTES);
        BULK_G2S(smem_u32(buf[0]),
                 x + (long long)tile0 * TILE_FLOATS, TILE_BYTES, mb);
    }

    const int r_in_tile = tid >> 4;    // 0..15, row within tile
    const int t         = tid & 15;    // 0..15, vert-group lane

    for (int i = 0; i < my_tiles; i++) {
        const int s = i & 1;

        // Prefetch tile i+1 into the other buffer. Its previous consumer
        // (tile i-1) finished before the __syncthreads that ended the prior
        // iteration, so the buffer is free.
        if (tid == 0 && (i + 1) < my_tiles) {
            const int s2 = (i + 1) & 1;
            const uint32_t mb = smem_u32(&mbar[s2]);
            MBAR_EXPECT_TX(mb, TILE_BYTES);
            BULK_G2S(smem_u32(buf[s2]),
                     x + (long long)(tile0 + i + 1) * TILE_FLOATS,
                     TILE_BYTES, mb);
        }

        // Wait for tile i. Buffer s is used on iterations s, s+2, ... so its
        // phase parity for this use is (i>>1)&1.
        MBAR_WAIT(smem_u32(&mbar[s]), (i >> 1) & 1);

        const float* rs = buf[s] + r_in_tile * DROW;
        const long long row = (long long)(tile0 + i) * TILE_ROWS + r_in_tile;

        const float px = rs[0], py = rs[1], pz = rs[2];
        const float qw = rs[3], qx = rs[4], qy = rs[5], qz = rs[6];

        // Unit-quaternion rotation matrix (matches reference formula).
        const float R00 = 1.f - 2.f * (qy * qy + qz * qz);
        const float R01 = 2.f * (qx * qy - qz * qw);
        const float R02 = 2.f * (qx * qz + qy * qw);
        const float R10 = 2.f * (qx * qy + qz * qw);
        const float R11 = 1.f - 2.f * (qx * qx + qz * qz);
        const float R12 = 2.f * (qy * qz - qx * qw);
        const float R20 = 2.f * (qx * qz - qy * qw);
        const float R21 = 2.f * (qy * qz + qx * qw);
        const float R22 = 1.f - 2.f * (qx * qx + qy * qy);

        float M[4][3], off[4];
#pragma unroll
        for (int p = 0; p < 4; p++) {
            const float e0 = sd[p * 3 + 0];
            const float e1 = sd[p * 3 + 1];
            const float e2 = sd[p * 3 + 2];
            M[p][0] = fmaf(e0, R00, fmaf(e1, R10, e2 * R20));
            M[p][1] = fmaf(e0, R01, fmaf(e1, R11, e2 * R21));
            M[p][2] = fmaf(e0, R02, fmaf(e1, R12, e2 * R22));
            off[p]  = fmaf(e0, px,  fmaf(e1, py,  e2 * pz));
        }

        float4* outv = reinterpret_cast<float4*>(out) + row * KVERTS;
#pragma unroll
        for (int j = 0; j < 4; j++) {
            const int k = t + 16 * j;
            const float v0 = rs[7 + 3 * k];
            const float v1 = rs[8 + 3 * k];
            const float v2 = rs[9 + 3 * k];
            float4 o;
            o.x = fmaf(M[0][0], v0, fmaf(M[0][1], v1, fmaf(M[0][2], v2, off[0])));
            o.y = fmaf(M[1][0], v0, fmaf(M[1][1], v1, fmaf(M[1][2], v2, off[1])));
            o.z = fmaf(M[2][0], v0, fmaf(M[2][1], v1, fmaf(M[2][2], v2, off[2])));
            o.w = fmaf(M[3][0], v0, fmaf(M[3][1], v1, fmaf(M[3][2], v2, off[3])));
            outv[k] = o;
        }

        __syncthreads();   // everyone done with buf[s] before it is refilled
    }
}

// Tail rows (B % 16 != 0) — not hit for B=131072, kept for safety.
__global__ void vde_tail_kernel(const float* __restrict__ x,
                                const float* __restrict__ dirs,
                                float* __restrict__ out,
                                int row_start, int B)
{
    const long long row = row_start + blockIdx.x;
    if (row >= B) return;
    const int k = threadIdx.x;           // 64 threads = 64 verts
    const float* rs = x + row * DROW;
    const float px = rs[0], py = rs[1], pz = rs[2];
    const float qw = rs[3], qx = rs[4], qy = rs[5], qz = rs[6];
    const float R00 = 1.f - 2.f * (qy * qy + qz * qz);
    const float R01 = 2.f * (qx * qy - qz * qw);
    const float R02 = 2.f * (qx * qz + qy * qw);
    const float R10 = 2.f * (qx * qy + qz * qw);
    const float R11 = 1.f - 2.f * (qx * qx + qz * qz);
    const float R12 = 2.f * (qy * qz - qx * qw);
    const float R20 = 2.f * (qx * qz - qy * qw);
    const float R21 = 2.f * (qy * qz + qx * qw);
    const float R22 = 1.f - 2.f * (qx * qx + qy * qy);
    const float v0 = rs[7 + 3 * k], v1 = rs[8 + 3 * k], v2 = rs[9 + 3 * k];
    const float wx = fmaf(R00, v0, fmaf(R01, v1, fmaf(R02, v2, px)));
    const float wy = fmaf(R10, v0, fmaf(R11, v1, fmaf(R12, v2, py)));
    const float wz = fmaf(R20, v0, fmaf(R21, v1, fmaf(R22, v2, pz)));
    float4 o;
    o.x = fmaf(dirs[0], wx, fmaf(dirs[1],  wy, dirs[2]  * wz));
    o.y = fmaf(dirs[3], wx, fmaf(dirs[4],  wy, dirs[5]  * wz));
    o.z = fmaf(dirs[6], wx, fmaf(dirs[7],  wy, dirs[8]  * wz));
    o.w = fmaf(dirs[9], wx, fmaf(dirs[10], wy, dirs[11] * wz));
    reinterpret_cast<float4*>(out)[row * KVERTS + k] = o;
}

extern "C" void kernel_launch(void* const* d_in, const int* in_sizes, int n_in,
                              void* d_out, int out_size)
{
    const float* x    = (const float*)d_in[0];
    const float* dirs = (const float*)d_in[1];
    float* out        = (float*)d_out;

    const int B = in_sizes[0] / DROW;          // (B,1,199) fp32
    const int n_tiles = B / TILE_ROWS;         // full tiles
    const int grid = (n_tiles + TPB_TILES - 1) / TPB_TILES;
    if (grid > 0)
        vde_kernel<<<grid, NTHREADS>>>(x, dirs, out, n_tiles);

    const int tail_rows = B - n_tiles * TILE_ROWS;
    if (tail_rows > 0)
        vde_tail_kernel<<<tail_rows, KVERTS>>>(x, dirs, out,
                                               n_tiles * TILE_ROWS, B);
}